// round 2
// baseline (speedup 1.0000x reference)
#include <cuda_runtime.h>
#include <math.h>

// Problem dims
#define TT    64
#define BB    1024
#define DETERD 512
#define STOCD  64
#define EMBD   1024
#define ACTD   6
#define MLPD   512
#define COUT   896   // DETER + 6*STOC

// Persistent scratch (no allocations allowed)
__device__ float g_deter[2 * BB * DETERD];
__device__ float g_stoc [2 * BB * STOCD];
__device__ float g_x    [BB * DETERD];
__device__ float g_p1   [BB * MLPD];
__device__ float g_q1   [BB * MLPD];

__device__ __forceinline__ float eluf(float x)  { return x > 0.f ? x : expm1f(x); }
__device__ __forceinline__ float sigm(float x)  { return 1.f / (1.f + expf(-x)); }
__device__ __forceinline__ float softp(float x) { return x > 0.f ? x + log1pf(expf(-x)) : log1pf(expf(x)); }

// ---------------------------------------------------------------------------
// K1: x = ELU(concat(stoc*nt, act) @ Wi + bi)   [B,70] @ [70,512]
// ---------------------------------------------------------------------------
__global__ __launch_bounds__(256) void k_input(
    const float* __restrict__ stoc_in, const float* __restrict__ act_t,
    const float* __restrict__ nt_t, const float* __restrict__ Wi,
    const float* __restrict__ bi, float* __restrict__ xout)
{
    const int BM = 64, BN = 64, BK = 16, TM = 4, TN = 4;
    __shared__ float As[BK][BM + 1];
    __shared__ float Bs[BK][BN + 1];
    int tid = threadIdx.x;
    int tcol = tid & 15, trow = tid >> 4;
    int rowBase = blockIdx.y * BM, colBase = blockIdx.x * BN;
    const int K = STOCD + ACTD; // 70
    float acc[TM][TN] = {};

    for (int k0 = 0; k0 < K; k0 += BK) {
        for (int i = tid; i < BK * BM; i += 256) {
            int kk = i & 15, m = i >> 4;
            int k = k0 + kk, b = rowBase + m;
            float v = 0.f;
            if (k < STOCD)      v = stoc_in[b * STOCD + k] * nt_t[b];
            else if (k < K)     v = act_t[b * ACTD + (k - STOCD)];
            As[kk][m] = v;
        }
        for (int i = tid; i < BK * BN; i += 256) {
            int n = i & 63, kk = i >> 6;
            int k = k0 + kk;
            Bs[kk][n] = (k < K) ? Wi[k * DETERD + colBase + n] : 0.f;
        }
        __syncthreads();
#pragma unroll
        for (int kk = 0; kk < BK; kk++) {
            float a[TM], bv[TN];
#pragma unroll
            for (int i = 0; i < TM; i++) a[i] = As[kk][trow * TM + i];
#pragma unroll
            for (int j = 0; j < TN; j++) bv[j] = Bs[kk][tcol * TN + j];
#pragma unroll
            for (int i = 0; i < TM; i++)
#pragma unroll
                for (int j = 0; j < TN; j++)
                    acc[i][j] = fmaf(a[i], bv[j], acc[i][j]);
        }
        __syncthreads();
    }
#pragma unroll
    for (int i = 0; i < TM; i++)
#pragma unroll
        for (int j = 0; j < TN; j++) {
            int b = rowBase + trow * TM + i, n = colBase + tcol * TN + j;
            xout[b * DETERD + n] = eluf(acc[i][j] + bi[n]);
        }
}

// ---------------------------------------------------------------------------
// K2: fused GRU.  6 accumulators per output: gi_{r,z,n} from x@W_ih^T,
// gh_{r,z,n} from (deter*nt)@W_hh^T. Epilogue computes deter_new, writes it
// to state buffer and output slice [0:512).
// ---------------------------------------------------------------------------
__global__ __launch_bounds__(256) void k_gru(
    const float* __restrict__ x, const float* __restrict__ deter_in,
    const float* __restrict__ nt_t,
    const float* __restrict__ W_ih, const float* __restrict__ W_hh,
    const float* __restrict__ b_ih, const float* __restrict__ b_hh,
    float* __restrict__ deter_out, float* __restrict__ out_t)
{
    const int BM = 64, BN = 32, BK = 16, TM = 4, TN = 2;
    __shared__ float Xs[BK][BM + 1];
    __shared__ float Hs[BK][BM + 1];
    __shared__ float Ws[6][BK][BN + 1];
    int tid = threadIdx.x;
    int tcol = tid & 15, trow = tid >> 4;
    int rowBase = blockIdx.y * BM, colBase = blockIdx.x * BN;
    float acc[6][TM][TN] = {};

    for (int k0 = 0; k0 < DETERD; k0 += BK) {
        for (int i = tid; i < BK * BM; i += 256) {
            int kk = i & 15, m = i >> 4;
            int k = k0 + kk, b = rowBase + m;
            Xs[kk][m] = x[b * DETERD + k];
            Hs[kk][m] = deter_in[b * DETERD + k] * nt_t[b];
        }
#pragma unroll
        for (int g = 0; g < 6; g++) {
            const float* W = (g < 3) ? W_ih : W_hh;
            int gofs = (g % 3) * DETERD;
            for (int i = tid; i < BK * BN; i += 256) {
                int kk = i & 15, nn = i >> 4;
                Ws[g][kk][nn] = W[(gofs + colBase + nn) * DETERD + k0 + kk];
            }
        }
        __syncthreads();
#pragma unroll
        for (int kk = 0; kk < BK; kk++) {
            float xa[TM], ha[TM];
#pragma unroll
            for (int i = 0; i < TM; i++) {
                xa[i] = Xs[kk][trow * TM + i];
                ha[i] = Hs[kk][trow * TM + i];
            }
            float wb[6][TN];
#pragma unroll
            for (int g = 0; g < 6; g++)
#pragma unroll
                for (int j = 0; j < TN; j++) wb[g][j] = Ws[g][kk][tcol * TN + j];
#pragma unroll
            for (int i = 0; i < TM; i++)
#pragma unroll
                for (int j = 0; j < TN; j++) {
                    acc[0][i][j] = fmaf(xa[i], wb[0][j], acc[0][i][j]);
                    acc[1][i][j] = fmaf(xa[i], wb[1][j], acc[1][i][j]);
                    acc[2][i][j] = fmaf(xa[i], wb[2][j], acc[2][i][j]);
                    acc[3][i][j] = fmaf(ha[i], wb[3][j], acc[3][i][j]);
                    acc[4][i][j] = fmaf(ha[i], wb[4][j], acc[4][i][j]);
                    acc[5][i][j] = fmaf(ha[i], wb[5][j], acc[5][i][j]);
                }
        }
        __syncthreads();
    }
#pragma unroll
    for (int i = 0; i < TM; i++)
#pragma unroll
        for (int j = 0; j < TN; j++) {
            int b = rowBase + trow * TM + i;
            int jj = colBase + tcol * TN + j;
            float ir  = acc[0][i][j] + b_ih[jj];
            float iz  = acc[1][i][j] + b_ih[DETERD + jj];
            float inn = acc[2][i][j] + b_ih[2 * DETERD + jj];
            float hr  = acc[3][i][j] + b_hh[jj];
            float hz  = acc[4][i][j] + b_hh[DETERD + jj];
            float hn  = acc[5][i][j] + b_hh[2 * DETERD + jj];
            float r = sigm(ir + hr);
            float z = sigm(iz + hz);
            float n = tanhf(inn + r * hn);
            float hj = deter_in[b * DETERD + jj] * nt_t[b];
            float dn = (1.f - z) * n + z * hj;
            deter_out[b * DETERD + jj] = dn;
            out_t[(size_t)b * COUT + jj] = dn;
        }
}

// ---------------------------------------------------------------------------
// K3: hidden layers of both heads (blockIdx.z: 0 = prior p1, 1 = posterior q1)
//   p1 = ELU(deter_new @ Wp1 + bp1)                   K=512
//   q1 = ELU(concat(deter_new, emb) @ Wq1 + bq1)      K=1536
// ---------------------------------------------------------------------------
__global__ __launch_bounds__(256) void k_mid(
    const float* __restrict__ deter, const float* __restrict__ emb_t,
    const float* __restrict__ Wp1, const float* __restrict__ bp1,
    const float* __restrict__ Wq1, const float* __restrict__ bq1,
    float* __restrict__ p1, float* __restrict__ q1)
{
    const int BM = 64, BN = 64, BK = 16, TM = 4, TN = 4;
    __shared__ float As[BK][BM + 1];
    __shared__ float Bs[BK][BN + 1];
    int z = blockIdx.z;
    const int K = z ? (DETERD + EMBD) : DETERD;
    const float* W   = z ? Wq1 : Wp1;
    const float* bia = z ? bq1 : bp1;
    float* outp      = z ? q1  : p1;

    int tid = threadIdx.x;
    int tcol = tid & 15, trow = tid >> 4;
    int rowBase = blockIdx.y * BM, colBase = blockIdx.x * BN;
    float acc[TM][TN] = {};

    for (int k0 = 0; k0 < K; k0 += BK) {
        for (int i = tid; i < BK * BM; i += 256) {
            int kk = i & 15, m = i >> 4;
            int k = k0 + kk, b = rowBase + m;
            float v = (k < DETERD) ? deter[b * DETERD + k]
                                   : emb_t[b * EMBD + (k - DETERD)];
            As[kk][m] = v;
        }
        for (int i = tid; i < BK * BN; i += 256) {
            int n = i & 63, kk = i >> 6;
            Bs[kk][n] = W[(k0 + kk) * MLPD + colBase + n];
        }
        __syncthreads();
#pragma unroll
        for (int kk = 0; kk < BK; kk++) {
            float a[TM], bv[TN];
#pragma unroll
            for (int i = 0; i < TM; i++) a[i] = As[kk][trow * TM + i];
#pragma unroll
            for (int j = 0; j < TN; j++) bv[j] = Bs[kk][tcol * TN + j];
#pragma unroll
            for (int i = 0; i < TM; i++)
#pragma unroll
                for (int j = 0; j < TN; j++)
                    acc[i][j] = fmaf(a[i], bv[j], acc[i][j]);
        }
        __syncthreads();
    }
#pragma unroll
    for (int i = 0; i < TM; i++)
#pragma unroll
        for (int j = 0; j < TN; j++) {
            int b = rowBase + trow * TM + i, n = colBase + tcol * TN + j;
            outp[b * MLPD + n] = eluf(acc[i][j] + bia[n]);
        }
}

// ---------------------------------------------------------------------------
// K4: output heads (blockIdx.z: 0 = prior, 1 = posterior).
// Dual accumulators per (b,i): mean col i and std col i+64 of W2 [512,128].
// Epilogue: softplus + MIN_STD, noise sample, writes 3 output slices; the
// posterior sample becomes the next-step stoc.
// ---------------------------------------------------------------------------
__global__ __launch_bounds__(256) void k_heads(
    const float* __restrict__ p1, const float* __restrict__ q1,
    const float* __restrict__ Wp2, const float* __restrict__ bp2,
    const float* __restrict__ Wq2, const float* __restrict__ bq2,
    const float* __restrict__ eps_p_t, const float* __restrict__ eps_q_t,
    float* __restrict__ out_t, float* __restrict__ stoc_out)
{
    const int BM = 64, BK = 16, TM = 4, TN = 4;
    __shared__ float As[BK][BM + 1];
    __shared__ float Bs[2][BK][STOCD + 1];
    int z = blockIdx.z;
    const float* A   = z ? q1  : p1;
    const float* W2  = z ? Wq2 : Wp2;
    const float* b2  = z ? bq2 : bp2;
    const float* eps = z ? eps_q_t : eps_p_t;
    const int obase  = z ? (DETERD + 3 * STOCD) : DETERD;

    int tid = threadIdx.x;
    int tcol = tid & 15, trow = tid >> 4;
    int rowBase = blockIdx.y * BM;
    float accm[TM][TN] = {}, accs[TM][TN] = {};

    for (int k0 = 0; k0 < MLPD; k0 += BK) {
        for (int i = tid; i < BK * BM; i += 256) {
            int kk = i & 15, m = i >> 4;
            As[kk][m] = A[(rowBase + m) * MLPD + k0 + kk];
        }
#pragma unroll
        for (int h = 0; h < 2; h++) {
            for (int i = tid; i < BK * STOCD; i += 256) {
                int ii = i & 63, kk = i >> 6;
                Bs[h][kk][ii] = W2[(k0 + kk) * (2 * STOCD) + h * STOCD + ii];
            }
        }
        __syncthreads();
#pragma unroll
        for (int kk = 0; kk < BK; kk++) {
            float a[TM], bm[TN], bs[TN];
#pragma unroll
            for (int i = 0; i < TM; i++) a[i] = As[kk][trow * TM + i];
#pragma unroll
            for (int j = 0; j < TN; j++) {
                bm[j] = Bs[0][kk][tcol * TN + j];
                bs[j] = Bs[1][kk][tcol * TN + j];
            }
#pragma unroll
            for (int i = 0; i < TM; i++)
#pragma unroll
                for (int j = 0; j < TN; j++) {
                    accm[i][j] = fmaf(a[i], bm[j], accm[i][j]);
                    accs[i][j] = fmaf(a[i], bs[j], accs[i][j]);
                }
        }
        __syncthreads();
    }
#pragma unroll
    for (int i = 0; i < TM; i++)
#pragma unroll
        for (int j = 0; j < TN; j++) {
            int b = rowBase + trow * TM + i;
            int ii = tcol * TN + j;
            float m = accm[i][j] + b2[ii];
            float s = softp(accs[i][j] + b2[STOCD + ii]) + 0.1f;
            float st = m + s * eps[b * STOCD + ii];
            size_t base = (size_t)b * COUT + obase;
            out_t[base + ii]              = m;
            out_t[base + STOCD + ii]      = s;
            out_t[base + 2 * STOCD + ii]  = st;
            if (z) stoc_out[b * STOCD + ii] = st;
        }
}

// ---------------------------------------------------------------------------
extern "C" void kernel_launch(void* const* d_in, const int* in_sizes, int n_in,
                              void* d_out, int out_size)
{
    const float* actions    = (const float*)d_in[0];
    const float* nonterm    = (const float*)d_in[1];
    const float* emb        = (const float*)d_in[2];
    const float* init_deter = (const float*)d_in[3];
    const float* init_stoc  = (const float*)d_in[4];
    const float* noise_p    = (const float*)d_in[5];
    const float* noise_q    = (const float*)d_in[6];
    const float* Wi   = (const float*)d_in[7];
    const float* bi   = (const float*)d_in[8];
    const float* W_ih = (const float*)d_in[9];
    const float* W_hh = (const float*)d_in[10];
    const float* b_ih = (const float*)d_in[11];
    const float* b_hh = (const float*)d_in[12];
    const float* Wp1  = (const float*)d_in[13];
    const float* bp1  = (const float*)d_in[14];
    const float* Wp2  = (const float*)d_in[15];
    const float* bp2  = (const float*)d_in[16];
    const float* Wq1  = (const float*)d_in[17];
    const float* bq1  = (const float*)d_in[18];
    const float* Wq2  = (const float*)d_in[19];
    const float* bq2  = (const float*)d_in[20];
    float* out = (float*)d_out;

    float *deterBuf, *stocBuf, *xBuf, *p1Buf, *q1Buf;
    cudaGetSymbolAddress((void**)&deterBuf, g_deter);
    cudaGetSymbolAddress((void**)&stocBuf,  g_stoc);
    cudaGetSymbolAddress((void**)&xBuf,     g_x);
    cudaGetSymbolAddress((void**)&p1Buf,    g_p1);
    cudaGetSymbolAddress((void**)&q1Buf,    g_q1);

    for (int t = 0; t < TT; t++) {
        const float* stoc_in  = t ? stocBuf  + ((t + 1) & 1) * BB * STOCD  : init_stoc;
        const float* deter_in = t ? deterBuf + ((t + 1) & 1) * BB * DETERD : init_deter;
        float* deter_out = deterBuf + (t & 1) * BB * DETERD;
        float* stoc_out  = stocBuf  + (t & 1) * BB * STOCD;
        const float* nt_t  = nonterm + (size_t)t * BB;
        const float* act_t = actions + (size_t)t * BB * ACTD;
        const float* emb_t = emb     + (size_t)t * BB * EMBD;
        float* out_t = out + (size_t)t * BB * COUT;

        k_input<<<dim3(8, 16), 256>>>(stoc_in, act_t, nt_t, Wi, bi, xBuf);
        k_gru  <<<dim3(16, 16), 256>>>(xBuf, deter_in, nt_t, W_ih, W_hh,
                                       b_ih, b_hh, deter_out, out_t);
        k_mid  <<<dim3(8, 16, 2), 256>>>(deter_out, emb_t, Wp1, bp1, Wq1, bq1,
                                         p1Buf, q1Buf);
        k_heads<<<dim3(1, 16, 2), 256>>>(p1Buf, q1Buf, Wp2, bp2, Wq2, bq2,
                                         noise_p + (size_t)t * BB * STOCD,
                                         noise_q + (size_t)t * BB * STOCD,
                                         out_t, stoc_out);
    }
}

// round 4
// speedup vs baseline: 1.1873x; 1.1873x over previous
#include <cuda_runtime.h>
#include <math.h>

#define TT    64
#define BB    1024
#define DETERD 512
#define STOCD  64
#define EMBD   1024
#define ACTD   6
#define MLPD   512
#define COUT   896

__device__ float g_deter[2 * BB * DETERD];
__device__ float g_stoc [2 * BB * STOCD];
__device__ float g_x    [BB * DETERD];
__device__ float g_p1   [BB * MLPD];
__device__ float g_q1   [BB * MLPD];

__device__ __forceinline__ float eluf(float x)  { return x > 0.f ? x : expm1f(x); }
__device__ __forceinline__ float sigm(float x)  { return 1.f / (1.f + expf(-x)); }
__device__ __forceinline__ float softp(float x) { return x > 0.f ? x + log1pf(expf(-x)) : log1pf(expf(x)); }

// ---------------------------------------------------------------------------
// K1: x = ELU(concat(stoc*nt, act) @ Wi + bi)   [B,70]@[70,512]
// BM=64,BN=64,BK=16, TM=TN=4, float4 smem reads.
// ---------------------------------------------------------------------------
__global__ __launch_bounds__(256) void k_input(
    const float* __restrict__ stoc_in, const float* __restrict__ act_t,
    const float* __restrict__ nt_t, const float* __restrict__ Wi,
    const float* __restrict__ bi, float* __restrict__ xout)
{
    __shared__ __align__(16) float As[16][68];
    __shared__ __align__(16) float Bs[16][64];
    const int K = STOCD + ACTD; // 70
    int tid = threadIdx.x;
    int tcol = tid & 15, trow = tid >> 4;
    int rowBase = blockIdx.y * 64, colBase = blockIdx.x * 64;
    float acc[4][4] = {};

    for (int k0 = 0; k0 < K; k0 += 16) {
        for (int i = tid; i < 16 * 64; i += 256) {
            int kk = i & 15, m = i >> 4;
            int k = k0 + kk, b = rowBase + m;
            float v = 0.f;
            if (k < STOCD)  v = stoc_in[b * STOCD + k] * nt_t[b];
            else if (k < K) v = act_t[b * ACTD + (k - STOCD)];
            As[kk][m] = v;
        }
        for (int i = tid; i < 16 * 64; i += 256) {
            int n = i & 63, kk = i >> 6;
            int k = k0 + kk;
            Bs[kk][n] = (k < K) ? Wi[k * DETERD + colBase + n] : 0.f;
        }
        __syncthreads();
#pragma unroll
        for (int kk = 0; kk < 16; kk++) {
            float4 a = *(const float4*)&As[kk][trow * 4];
            float4 b = *(const float4*)&Bs[kk][tcol * 4];
            float av[4] = {a.x, a.y, a.z, a.w};
            float bv[4] = {b.x, b.y, b.z, b.w};
#pragma unroll
            for (int i = 0; i < 4; i++)
#pragma unroll
                for (int j = 0; j < 4; j++)
                    acc[i][j] = fmaf(av[i], bv[j], acc[i][j]);
        }
        __syncthreads();
    }
#pragma unroll
    for (int i = 0; i < 4; i++)
#pragma unroll
        for (int j = 0; j < 4; j++) {
            int b = rowBase + trow * 4 + i, n = colBase + tcol * 4 + j;
            xout[b * DETERD + n] = eluf(acc[i][j] + bi[n]);
        }
}

// ---------------------------------------------------------------------------
// K2: fused GRU. BM=64, BN=32/gate (x16 tiles), BK=16, TM=4, TN=2, 6 gates.
// Vectorized smem reads: 2x LDS.128 (x,h) + 6x LDS.64 (gates) : 48 FMA.
// ---------------------------------------------------------------------------
__global__ __launch_bounds__(256) void k_gru(
    const float* __restrict__ x, const float* __restrict__ deter_in,
    const float* __restrict__ nt_t,
    const float* __restrict__ W_ih, const float* __restrict__ W_hh,
    const float* __restrict__ b_ih, const float* __restrict__ b_hh,
    float* __restrict__ deter_out, float* __restrict__ out_t)
{
    __shared__ __align__(16) float Xs[16][68];
    __shared__ __align__(16) float Hs[16][68];
    __shared__ __align__(16) float Ws[6][16][32];
    int tid = threadIdx.x;
    int tcol = tid & 15, trow = tid >> 4;
    int rowBase = blockIdx.y * 64, colBase = blockIdx.x * 32;
    float acc[6][4][2] = {};

    for (int k0 = 0; k0 < DETERD; k0 += 16) {
        for (int i = tid; i < 16 * 64; i += 256) {
            int kk = i & 15, m = i >> 4;
            int k = k0 + kk, b = rowBase + m;
            Xs[kk][m] = x[b * DETERD + k];
            Hs[kk][m] = deter_in[b * DETERD + k] * nt_t[b];
        }
        for (int i = tid; i < 6 * 16 * 32; i += 256) {
            int g = i >> 9, rem = i & 511;
            int kk = rem & 15, nn = rem >> 4;
            const float* W = (g < 3) ? W_ih : W_hh;
            int gofs = (g % 3) * DETERD;
            Ws[g][kk][nn] = W[(gofs + colBase + nn) * DETERD + k0 + kk];
        }
        __syncthreads();
#pragma unroll
        for (int kk = 0; kk < 16; kk++) {
            float4 xv4 = *(const float4*)&Xs[kk][trow * 4];
            float4 hv4 = *(const float4*)&Hs[kk][trow * 4];
            float xa[4] = {xv4.x, xv4.y, xv4.z, xv4.w};
            float ha[4] = {hv4.x, hv4.y, hv4.z, hv4.w};
            float wb[6][2];
#pragma unroll
            for (int g = 0; g < 6; g++) {
                float2 w2 = *(const float2*)&Ws[g][kk][tcol * 2];
                wb[g][0] = w2.x; wb[g][1] = w2.y;
            }
#pragma unroll
            for (int i = 0; i < 4; i++)
#pragma unroll
                for (int j = 0; j < 2; j++) {
                    acc[0][i][j] = fmaf(xa[i], wb[0][j], acc[0][i][j]);
                    acc[1][i][j] = fmaf(xa[i], wb[1][j], acc[1][i][j]);
                    acc[2][i][j] = fmaf(xa[i], wb[2][j], acc[2][i][j]);
                    acc[3][i][j] = fmaf(ha[i], wb[3][j], acc[3][i][j]);
                    acc[4][i][j] = fmaf(ha[i], wb[4][j], acc[4][i][j]);
                    acc[5][i][j] = fmaf(ha[i], wb[5][j], acc[5][i][j]);
                }
        }
        __syncthreads();
    }
#pragma unroll
    for (int i = 0; i < 4; i++)
#pragma unroll
        for (int j = 0; j < 2; j++) {
            int b = rowBase + trow * 4 + i;
            int jj = colBase + tcol * 2 + j;
            float ir  = acc[0][i][j] + b_ih[jj];
            float iz  = acc[1][i][j] + b_ih[DETERD + jj];
            float inn = acc[2][i][j] + b_ih[2 * DETERD + jj];
            float hr  = acc[3][i][j] + b_hh[jj];
            float hz  = acc[4][i][j] + b_hh[DETERD + jj];
            float hn  = acc[5][i][j] + b_hh[2 * DETERD + jj];
            float r = sigm(ir + hr);
            float z = sigm(iz + hz);
            float n = tanhf(inn + r * hn);
            float hj = deter_in[b * DETERD + jj] * nt_t[b];
            float dn = (1.f - z) * n + z * hj;
            deter_out[b * DETERD + jj] = dn;
            out_t[(size_t)b * COUT + jj] = dn;
        }
}

// ---------------------------------------------------------------------------
// K3: hidden layers of both heads. BM=64,BN=64,BK=16, TM=TN=4.
// z=0: p1 = ELU(deter@Wp1+bp1) K=512;  z=1: q1 = ELU([deter,emb]@Wq1+bq1) K=1536
// ---------------------------------------------------------------------------
__global__ __launch_bounds__(256) void k_mid(
    const float* __restrict__ deter, const float* __restrict__ emb_t,
    const float* __restrict__ Wp1, const float* __restrict__ bp1,
    const float* __restrict__ Wq1, const float* __restrict__ bq1,
    float* __restrict__ p1, float* __restrict__ q1)
{
    __shared__ __align__(16) float As[16][68];
    __shared__ __align__(16) float Bs[16][64];
    int z = blockIdx.z;
    const int K = z ? (DETERD + EMBD) : DETERD;
    const float* W   = z ? Wq1 : Wp1;
    const float* bia = z ? bq1 : bp1;
    float* outp      = z ? q1  : p1;

    int tid = threadIdx.x;
    int tcol = tid & 15, trow = tid >> 4;
    int rowBase = blockIdx.y * 64, colBase = blockIdx.x * 64;
    float acc[4][4] = {};

    for (int k0 = 0; k0 < K; k0 += 16) {
        for (int i = tid; i < 16 * 64; i += 256) {
            int kk = i & 15, m = i >> 4;
            int k = k0 + kk, b = rowBase + m;
            As[kk][m] = (k < DETERD) ? deter[b * DETERD + k]
                                     : emb_t[b * EMBD + (k - DETERD)];
        }
        for (int i = tid; i < 16 * 64; i += 256) {
            int n = i & 63, kk = i >> 6;
            Bs[kk][n] = W[(k0 + kk) * MLPD + colBase + n];
        }
        __syncthreads();
#pragma unroll
        for (int kk = 0; kk < 16; kk++) {
            float4 a = *(const float4*)&As[kk][trow * 4];
            float4 b = *(const float4*)&Bs[kk][tcol * 4];
            float av[4] = {a.x, a.y, a.z, a.w};
            float bv[4] = {b.x, b.y, b.z, b.w};
#pragma unroll
            for (int i = 0; i < 4; i++)
#pragma unroll
                for (int j = 0; j < 4; j++)
                    acc[i][j] = fmaf(av[i], bv[j], acc[i][j]);
        }
        __syncthreads();
    }
#pragma unroll
    for (int i = 0; i < 4; i++)
#pragma unroll
        for (int j = 0; j < 4; j++) {
            int b = rowBase + trow * 4 + i, n = colBase + tcol * 4 + j;
            outp[b * MLPD + n] = eluf(acc[i][j] + bia[n]);
        }
}

// ---------------------------------------------------------------------------
// K4: output heads. BM=32, BN=128 (mean||std), BK=16.
// 256 thr: tcol=tid&31 (TN=4 over 128 cols), trow=tid>>5 (TM=4 over 32 rows).
// std-half threads compute softplus and exchange s via smem so mean-half
// threads can form the sample st = m + s*eps.
// ---------------------------------------------------------------------------
__global__ __launch_bounds__(256) void k_heads(
    const float* __restrict__ p1, const float* __restrict__ q1,
    const float* __restrict__ Wp2, const float* __restrict__ bp2,
    const float* __restrict__ Wq2, const float* __restrict__ bq2,
    const float* __restrict__ eps_p_t, const float* __restrict__ eps_q_t,
    float* __restrict__ out_t, float* __restrict__ stoc_out)
{
    __shared__ __align__(16) float As[16][36];
    __shared__ __align__(16) float Bs[16][128];
    __shared__ __align__(16) float Ss[32][64];
    int z = blockIdx.z;
    const float* A   = z ? q1  : p1;
    const float* W2  = z ? Wq2 : Wp2;
    const float* b2  = z ? bq2 : bp2;
    const float* eps = z ? eps_q_t : eps_p_t;
    const int obase  = z ? (DETERD + 3 * STOCD) : DETERD;

    int tid = threadIdx.x;
    int tcol = tid & 31, trow = tid >> 5;
    int rowBase = blockIdx.y * 32;
    float acc[4][4] = {};

    for (int k0 = 0; k0 < MLPD; k0 += 16) {
        for (int i = tid; i < 16 * 32; i += 256) {
            int kk = i & 15, m = i >> 4;
            As[kk][m] = A[(rowBase + m) * MLPD + k0 + kk];
        }
        for (int i = tid; i < 16 * 128; i += 256) {
            int n = i & 127, kk = i >> 7;
            Bs[kk][n] = W2[(k0 + kk) * (2 * STOCD) + n];
        }
        __syncthreads();
#pragma unroll
        for (int kk = 0; kk < 16; kk++) {
            float4 a = *(const float4*)&As[kk][trow * 4];
            float4 b = *(const float4*)&Bs[kk][tcol * 4];
            float av[4] = {a.x, a.y, a.z, a.w};
            float bv[4] = {b.x, b.y, b.z, b.w};
#pragma unroll
            for (int i = 0; i < 4; i++)
#pragma unroll
                for (int j = 0; j < 4; j++)
                    acc[i][j] = fmaf(av[i], bv[j], acc[i][j]);
        }
        __syncthreads();
    }

    if (tcol >= 16) { // std half: cols 64..127
#pragma unroll
        for (int i = 0; i < 4; i++)
#pragma unroll
            for (int j = 0; j < 4; j++) {
                int cc = tcol * 4 + j;           // 64..127
                int ii = cc - STOCD;             // 0..63
                int r  = trow * 4 + i;           // 0..31
                int b  = rowBase + r;
                float s = softp(acc[i][j] + b2[cc]) + 0.1f;
                Ss[r][ii] = s;
                out_t[(size_t)b * COUT + obase + STOCD + ii] = s;
            }
    }
    __syncthreads();
    if (tcol < 16) { // mean half: cols 0..63
#pragma unroll
        for (int i = 0; i < 4; i++)
#pragma unroll
            for (int j = 0; j < 4; j++) {
                int ii = tcol * 4 + j;           // 0..63
                int r  = trow * 4 + i;
                int b  = rowBase + r;
                float m = acc[i][j] + b2[ii];
                float s = Ss[r][ii];
                float st = m + s * eps[b * STOCD + ii];
                size_t base = (size_t)b * COUT + obase;
                out_t[base + ii]             = m;
                out_t[base + 2 * STOCD + ii] = st;
                if (z) stoc_out[b * STOCD + ii] = st;
            }
    }
}

// ---------------------------------------------------------------------------
extern "C" void kernel_launch(void* const* d_in, const int* in_sizes, int n_in,
                              void* d_out, int out_size)
{
    const float* actions    = (const float*)d_in[0];
    const float* nonterm    = (const float*)d_in[1];
    const float* emb        = (const float*)d_in[2];
    const float* init_deter = (const float*)d_in[3];
    const float* init_stoc  = (const float*)d_in[4];
    const float* noise_p    = (const float*)d_in[5];
    const float* noise_q    = (const float*)d_in[6];
    const float* Wi   = (const float*)d_in[7];
    const float* bi   = (const float*)d_in[8];
    const float* W_ih = (const float*)d_in[9];
    const float* W_hh = (const float*)d_in[10];
    const float* b_ih = (const float*)d_in[11];
    const float* b_hh = (const float*)d_in[12];
    const float* Wp1  = (const float*)d_in[13];
    const float* bp1  = (const float*)d_in[14];
    const float* Wp2  = (const float*)d_in[15];
    const float* bp2  = (const float*)d_in[16];
    const float* Wq1  = (const float*)d_in[17];
    const float* bq1  = (const float*)d_in[18];
    const float* Wq2  = (const float*)d_in[19];
    const float* bq2  = (const float*)d_in[20];
    float* out = (float*)d_out;

    float *deterBuf, *stocBuf, *xBuf, *p1Buf, *q1Buf;
    cudaGetSymbolAddress((void**)&deterBuf, g_deter);
    cudaGetSymbolAddress((void**)&stocBuf,  g_stoc);
    cudaGetSymbolAddress((void**)&xBuf,     g_x);
    cudaGetSymbolAddress((void**)&p1Buf,    g_p1);
    cudaGetSymbolAddress((void**)&q1Buf,    g_q1);

    for (int t = 0; t < TT; t++) {
        const float* stoc_in  = t ? stocBuf  + ((t + 1) & 1) * BB * STOCD  : init_stoc;
        const float* deter_in = t ? deterBuf + ((t + 1) & 1) * BB * DETERD : init_deter;
        float* deter_out = deterBuf + (t & 1) * BB * DETERD;
        float* stoc_out  = stocBuf  + (t & 1) * BB * STOCD;
        const float* nt_t  = nonterm + (size_t)t * BB;
        const float* act_t = actions + (size_t)t * BB * ACTD;
        const float* emb_t = emb     + (size_t)t * BB * EMBD;
        float* out_t = out + (size_t)t * BB * COUT;

        k_input<<<dim3(8, 16), 256>>>(stoc_in, act_t, nt_t, Wi, bi, xBuf);
        k_gru  <<<dim3(16, 16), 256>>>(xBuf, deter_in, nt_t, W_ih, W_hh,
                                       b_ih, b_hh, deter_out, out_t);
        k_mid  <<<dim3(8, 16, 2), 256>>>(deter_out, emb_t, Wp1, bp1, Wq1, bq1,
                                         p1Buf, q1Buf);
        k_heads<<<dim3(1, 32, 2), 256>>>(p1Buf, q1Buf, Wp2, bp2, Wq2, bq2,
                                         noise_p + (size_t)t * BB * STOCD,
                                         noise_q + (size_t)t * BB * STOCD,
                                         out_t, stoc_out);
    }
}

// round 6
// speedup vs baseline: 5.1636x; 4.3490x over previous
#include <cuda_runtime.h>
#include <cuda_fp16.h>
#include <math.h>
#include <stdint.h>

#define TT     64
#define BBATCH 1024
#define DET    512
#define STO    64
#define EMBD   1024
#define ACTD   6
#define MLPD   512
#define COUT   896

// ---------------- persistent scratch (no allocs allowed) --------------------
__device__ __align__(16) __half g_Wi16 [512 * 128];
__device__ __align__(16) __half g_Wih16[1536 * 512];
__device__ __align__(16) __half g_Whh16[1536 * 512];
__device__ __align__(16) __half g_Wp116[512 * 512];
__device__ __align__(16) __half g_Wq116[512 * 1536];
__device__ __align__(16) __half g_Wp216[128 * 512];
__device__ __align__(16) __half g_Wq216[128 * 512];
__device__ __align__(16) __half g_x16  [BBATCH * 512];
__device__ __align__(16) __half g_det16[BBATCH * 512];
__device__ __align__(16) __half g_p116 [BBATCH * 512];
__device__ __align__(16) __half g_q116 [BBATCH * 512];
__device__ __align__(16) float  g_deter[2 * BBATCH * 512];
__device__ __align__(16) float  g_stoc [2 * BBATCH * 64];
__device__ __align__(16) float  g_gi   [BBATCH * 1536];
__device__ __align__(16) float  g_gh   [BBATCH * 1536];

// ---------------- math helpers ---------------------------------------------
__device__ __forceinline__ float eluf(float x)  { return x > 0.f ? x : expm1f(x); }
__device__ __forceinline__ float sigm(float x)  { return 1.f / (1.f + expf(-x)); }
__device__ __forceinline__ float softp(float x) { return x > 0.f ? x + log1pf(expf(-x)) : log1pf(expf(x)); }

// ---------------- MMA primitives -------------------------------------------
__device__ __forceinline__ void ldm_x4(uint32_t* r, const void* p) {
    uint32_t a;
    asm("{ .reg .u64 t; cvta.to.shared.u64 t, %1; cvt.u32.u64 %0, t; }" : "=r"(a) : "l"(p));
    asm volatile("ldmatrix.sync.aligned.m8n8.x4.shared.b16 {%0,%1,%2,%3}, [%4];"
                 : "=r"(r[0]), "=r"(r[1]), "=r"(r[2]), "=r"(r[3]) : "r"(a));
}
__device__ __forceinline__ void ldm_x2(uint32_t* r, const void* p) {
    uint32_t a;
    asm("{ .reg .u64 t; cvta.to.shared.u64 t, %1; cvt.u32.u64 %0, t; }" : "=r"(a) : "l"(p));
    asm volatile("ldmatrix.sync.aligned.m8n8.x2.shared.b16 {%0,%1}, [%2];"
                 : "=r"(r[0]), "=r"(r[1]) : "r"(a));
}
__device__ __forceinline__ void mma16816(float* c, const uint32_t* a, const uint32_t* b) {
    asm volatile(
        "mma.sync.aligned.m16n8k16.row.col.f32.f16.f16.f32 "
        "{%0,%1,%2,%3}, {%4,%5,%6,%7}, {%8,%9}, {%0,%1,%2,%3};"
        : "+f"(c[0]), "+f"(c[1]), "+f"(c[2]), "+f"(c[3])
        : "r"(a[0]), "r"(a[1]), "r"(a[2]), "r"(a[3]), "r"(b[0]), "r"(b[1]));
}

// ---------------- A-tile sources -------------------------------------------
#define SRC_F16    0
#define SRC_DETER  1
#define SRC_INPUT  2
#define SRC_CONCAT 3

template<int ASRC, int BW>
__device__ __forceinline__ void fetch_tiles(
    int k0, int rowBase, int colBase,
    const __half* Af16, int lda,
    const float* Aa, const float* Ab, const float* nt,
    const __half* Bw, int ldb,
    uint32_t* aA, uint32_t* aB)
{
    const int tid = threadIdx.x;
#pragma unroll
    for (int i = 0; i < 16; i++) {
        int w = tid + i * 256;
        int row = w >> 5, kp = w & 31;
        int b = rowBase + row;
        int k = k0 + kp * 2;
        __half2 v;
        if (ASRC == SRC_F16) {
            v = *(const __half2*)(Af16 + (size_t)b * lda + k);
        } else if (ASRC == SRC_DETER) {
            float2 f = *(const float2*)(Aa + (size_t)b * DET + k);
            float s = nt[b];
            v = __floats2half2_rn(f.x * s, f.y * s);
        } else if (ASRC == SRC_CONCAT) {
            if (k < DET) {
                v = *(const __half2*)(Af16 + (size_t)b * DET + k);
            } else {
                float2 f = *(const float2*)(Aa + (size_t)b * EMBD + (k - DET));
                v = __floats2half2_rn(f.x, f.y);
            }
        } else { // SRC_INPUT: [stoc*nt | act | 0]
            float s = nt[b];
            float lo = (k < STO) ? Aa[b * STO + k] * s
                     : ((k < STO + ACTD) ? Ab[b * ACTD + (k - STO)] : 0.f);
            int k1 = k + 1;
            float hi = (k1 < STO) ? Aa[b * STO + k1] * s
                     : ((k1 < STO + ACTD) ? Ab[b * ACTD + (k1 - STO)] : 0.f);
            v = __floats2half2_rn(lo, hi);
        }
        aA[i] = *(uint32_t*)&v;
    }
#pragma unroll
    for (int i = 0; i < BW; i++) {
        int w = tid + i * 256;
        int row = w >> 5, kp = w & 31;
        __half2 v = *(const __half2*)(Bw + (size_t)(colBase + row) * ldb + k0 + kp * 2);
        aB[i] = *(uint32_t*)&v;
    }
}

// ---------------- GEMM core: C[128 x NCOLS] = A[128xK] * B[NCOLS x K]^T -----
// 8 warps: warpM = w&3 (32 rows), warpN = w>>2 (NCOLS/2 cols).
// cacc layout: [2 mtiles][NT ntiles][4], NT = NCOLS/16.
template<int NCOLS, int ASRC>
__device__ __forceinline__ void gemm_core(
    int kchunks,
    const __half* Af16, int lda,
    const float* Aa, const float* Ab, const float* nt,
    const __half* Bw, int ldb,
    int rowBase, int colBase,
    __half (*sA)[72], __half (*sB)[72],
    float* cacc)
{
    constexpr int BW = NCOLS / 8;
    constexpr int NT = NCOLS / 16;
    const int tid = threadIdx.x, lane = tid & 31, w = tid >> 5;
    const int mrow = (w & 3) * 32;
    const int ncol = (w >> 2) * (NCOLS / 2);

#pragma unroll
    for (int i = 0; i < 2 * NT * 4; i++) cacc[i] = 0.f;

    uint32_t aA[16], aB[BW];
    fetch_tiles<ASRC, BW>(0, rowBase, colBase, Af16, lda, Aa, Ab, nt, Bw, ldb, aA, aB);

    for (int c = 0; c < kchunks; c++) {
#pragma unroll
        for (int i = 0; i < 16; i++) {
            int ww = tid + i * 256;
            int row = ww >> 5, kp = ww & 31;
            *(uint32_t*)&sA[row][kp * 2] = aA[i];
        }
#pragma unroll
        for (int i = 0; i < BW; i++) {
            int ww = tid + i * 256;
            int row = ww >> 5, kp = ww & 31;
            *(uint32_t*)&sB[row][kp * 2] = aB[i];
        }
        __syncthreads();

#pragma unroll
        for (int kk = 0; kk < 4; kk++) {
            int kb = kk * 16;
            uint32_t afr[2][4];
#pragma unroll
            for (int mt = 0; mt < 2; mt++)
                ldm_x4(afr[mt], &sA[mrow + mt * 16 + (lane & 15)][kb + ((lane >> 4) << 3)]);
            uint32_t bfr[NT][2];
#pragma unroll
            for (int nt2 = 0; nt2 < NT; nt2++)
                ldm_x2(bfr[nt2], &sB[ncol + nt2 * 8 + (lane & 7)][kb + (((lane >> 3) & 1) << 3)]);
#pragma unroll
            for (int mt = 0; mt < 2; mt++)
#pragma unroll
                for (int nt2 = 0; nt2 < NT; nt2++)
                    mma16816(cacc + (mt * NT + nt2) * 4, afr[mt], bfr[nt2]);
        }

        if (c + 1 < kchunks)
            fetch_tiles<ASRC, BW>((c + 1) * 64, rowBase, colBase,
                                  Af16, lda, Aa, Ab, nt, Bw, ldb, aA, aB);
        __syncthreads();
    }
}

// fragment -> (local row, local col) helpers
#define FRAG_ROW(mrow, mt, lane, half) ((mrow) + (mt) * 16 + ((lane) >> 2) + ((half) ? 8 : 0))
#define FRAG_COL(ncol, nt2, lane)      ((ncol) + (nt2) * 8 + ((lane) & 3) * 2)

// ---------------- Kernels --------------------------------------------------

__global__ __launch_bounds__(256) void k_prep(
    const float* __restrict__ src, __half* __restrict__ dst,
    int total, int srcK, int dstK, int srcN, int trans)
{
    for (int idx = blockIdx.x * 256 + threadIdx.x; idx < total; idx += gridDim.x * 256) {
        int n = idx / dstK, k = idx % dstK;
        float v = 0.f;
        if (k < srcK)
            v = trans ? src[(size_t)k * srcN + n] : src[(size_t)n * srcK + k];
        dst[idx] = __float2half(v);
    }
}

// G1: x16 = fp16(ELU(cat(stoc*nt, act) @ Wi + bi))   grid(8,8), NCOLS=64
__global__ __launch_bounds__(256) void kg_x(
    const float* __restrict__ stoc_in, const float* __restrict__ act_t,
    const float* __restrict__ nt, const float* __restrict__ bi)
{
    __shared__ __align__(16) __half sA[128][72];
    __shared__ __align__(16) __half sB[64][72];
    int rowBase = blockIdx.y * 128, colBase = blockIdx.x * 64;
    float c[2 * 4 * 4];
    gemm_core<64, SRC_INPUT>(2, nullptr, 0, stoc_in, act_t, nt,
                             g_Wi16, 128, rowBase, colBase, sA, sB, c);
    int lane = threadIdx.x & 31, w = threadIdx.x >> 5;
    int mrow = (w & 3) * 32, ncol = (w >> 2) * 32;
#pragma unroll
    for (int mt = 0; mt < 2; mt++)
#pragma unroll
        for (int nt2 = 0; nt2 < 4; nt2++) {
            float* cc = c + (mt * 4 + nt2) * 4;
            int col = colBase + FRAG_COL(ncol, nt2, lane);
#pragma unroll
            for (int h = 0; h < 2; h++) {
                int b = rowBase + FRAG_ROW(mrow, mt, lane, h);
                float v0 = eluf(cc[h * 2]     + bi[col]);
                float v1 = eluf(cc[h * 2 + 1] + bi[col + 1]);
                *(__half2*)(g_x16 + (size_t)b * 512 + col) = __floats2half2_rn(v0, v1);
            }
        }
}

// G2/G3: gi = x16 @ W_ih^T (z=0); gh = (deter*nt) @ W_hh^T (z=1)   grid(24,8,2)
__global__ __launch_bounds__(256) void kg_gru(
    const float* __restrict__ deter_in, const float* __restrict__ nt)
{
    __shared__ __align__(16) __half sA[128][72];
    __shared__ __align__(16) __half sB[64][72];
    int z = blockIdx.z;
    int rowBase = blockIdx.y * 128, colBase = blockIdx.x * 64;
    float c[2 * 4 * 4];
    if (z)
        gemm_core<64, SRC_DETER>(8, nullptr, 0, deter_in, nullptr, nt,
                                 g_Whh16, 512, rowBase, colBase, sA, sB, c);
    else
        gemm_core<64, SRC_F16>(8, g_x16, 512, nullptr, nullptr, nullptr,
                               g_Wih16, 512, rowBase, colBase, sA, sB, c);
    float* outp = z ? g_gh : g_gi;
    int lane = threadIdx.x & 31, w = threadIdx.x >> 5;
    int mrow = (w & 3) * 32, ncol = (w >> 2) * 32;
#pragma unroll
    for (int mt = 0; mt < 2; mt++)
#pragma unroll
        for (int nt2 = 0; nt2 < 4; nt2++) {
            float* cc = c + (mt * 4 + nt2) * 4;
            int col = colBase + FRAG_COL(ncol, nt2, lane);
#pragma unroll
            for (int h = 0; h < 2; h++) {
                int b = rowBase + FRAG_ROW(mrow, mt, lane, h);
                *(float2*)(outp + (size_t)b * 1536 + col) = make_float2(cc[h * 2], cc[h * 2 + 1]);
            }
        }
}

// E1: GRU gates elementwise  grid(2048)
__global__ __launch_bounds__(256) void ke_gru(
    const float* __restrict__ deter_in, const float* __restrict__ nt,
    const float* __restrict__ b_ih, const float* __restrict__ b_hh,
    float* __restrict__ deter_out, float* __restrict__ out_t)
{
    int idx = blockIdx.x * 256 + threadIdx.x;
    int b = idx >> 9, j = idx & 511;
    float ir  = g_gi[(size_t)b * 1536 + j]        + b_ih[j];
    float iz  = g_gi[(size_t)b * 1536 + 512 + j]  + b_ih[512 + j];
    float inn = g_gi[(size_t)b * 1536 + 1024 + j] + b_ih[1024 + j];
    float hr  = g_gh[(size_t)b * 1536 + j]        + b_hh[j];
    float hz  = g_gh[(size_t)b * 1536 + 512 + j]  + b_hh[512 + j];
    float hn  = g_gh[(size_t)b * 1536 + 1024 + j] + b_hh[1024 + j];
    float h = deter_in[(size_t)b * 512 + j] * nt[b];
    float r = sigm(ir + hr);
    float z = sigm(iz + hz);
    float n = tanhf(inn + r * hn);
    float dn = (1.f - z) * n + z * h;
    deter_out[(size_t)b * 512 + j] = dn;
    g_det16[(size_t)b * 512 + j] = __float2half(dn);
    out_t[(size_t)b * COUT + j] = dn;
}

// G4/G5: p1 (z=0, K=512) / q1 (z=1, K=1536) hidden layers   grid(8,8,2)
__global__ __launch_bounds__(256) void kg_mid(
    const float* __restrict__ emb_t,
    const float* __restrict__ bp1, const float* __restrict__ bq1)
{
    __shared__ __align__(16) __half sA[128][72];
    __shared__ __align__(16) __half sB[64][72];
    int z = blockIdx.z;
    int rowBase = blockIdx.y * 128, colBase = blockIdx.x * 64;
    float c[2 * 4 * 4];
    if (z)
        gemm_core<64, SRC_CONCAT>(24, g_det16, 512, emb_t, nullptr, nullptr,
                                  g_Wq116, 1536, rowBase, colBase, sA, sB, c);
    else
        gemm_core<64, SRC_F16>(8, g_det16, 512, nullptr, nullptr, nullptr,
                               g_Wp116, 512, rowBase, colBase, sA, sB, c);
    const float* bia = z ? bq1 : bp1;
    __half* outp = z ? g_q116 : g_p116;
    int lane = threadIdx.x & 31, w = threadIdx.x >> 5;
    int mrow = (w & 3) * 32, ncol = (w >> 2) * 32;
#pragma unroll
    for (int mt = 0; mt < 2; mt++)
#pragma unroll
        for (int nt2 = 0; nt2 < 4; nt2++) {
            float* cc = c + (mt * 4 + nt2) * 4;
            int col = colBase + FRAG_COL(ncol, nt2, lane);
#pragma unroll
            for (int h = 0; h < 2; h++) {
                int b = rowBase + FRAG_ROW(mrow, mt, lane, h);
                float v0 = eluf(cc[h * 2]     + bia[col]);
                float v1 = eluf(cc[h * 2 + 1] + bia[col + 1]);
                *(__half2*)(outp + (size_t)b * 512 + col) = __floats2half2_rn(v0, v1);
            }
        }
}

// G6/G7: heads.  z=0 prior, z=1 posterior.  grid(1,8,2), NCOLS=128.
// warpN=0 -> mean cols 0..63, warpN=1 -> std cols 64..127; exchange s via smem.
__global__ __launch_bounds__(256) void kg_head(
    const float* __restrict__ bp2, const float* __restrict__ bq2,
    const float* __restrict__ eps_p, const float* __restrict__ eps_q,
    float* __restrict__ out_t, float* __restrict__ stoc_out)
{
    __shared__ __align__(16) __half sA[128][72];
    __shared__ __align__(16) __half sB[128][72];
    int z = blockIdx.z;
    int rowBase = blockIdx.y * 128;
    float c[2 * 8 * 4];
    if (z)
        gemm_core<128, SRC_F16>(8, g_q116, 512, nullptr, nullptr, nullptr,
                                g_Wq216, 512, rowBase, 0, sA, sB, c);
    else
        gemm_core<128, SRC_F16>(8, g_p116, 512, nullptr, nullptr, nullptr,
                                g_Wp216, 512, rowBase, 0, sA, sB, c);
    const float* b2  = z ? bq2 : bp2;
    const float* eps = z ? eps_q : eps_p;
    const int obase  = z ? (DET + 3 * STO) : DET;
    int lane = threadIdx.x & 31, w = threadIdx.x >> 5;
    int mrow = (w & 3) * 32, warpN = w >> 2;

    float (*Ss)[64] = (float(*)[64])sA;   // overlay 128x64 fp32 = 32KB on sA/sB
    __syncthreads();

    if (warpN == 1) { // std half
#pragma unroll
        for (int mt = 0; mt < 2; mt++)
#pragma unroll
            for (int nt2 = 0; nt2 < 8; nt2++) {
                float* cc = c + (mt * 8 + nt2) * 4;
                int col = 64 + nt2 * 8 + (lane & 3) * 2;   // 64..127
#pragma unroll
                for (int h = 0; h < 2; h++) {
                    int rl = FRAG_ROW(mrow, mt, lane, h);
                    int b = rowBase + rl;
#pragma unroll
                    for (int q = 0; q < 2; q++) {
                        int ii = col + q - 64;
                        float s = softp(cc[h * 2 + q] + b2[col + q]) + 0.1f;
                        Ss[rl][ii] = s;
                        out_t[(size_t)b * COUT + obase + STO + ii] = s;
                    }
                }
            }
    }
    __syncthreads();
    if (warpN == 0) { // mean half
#pragma unroll
        for (int mt = 0; mt < 2; mt++)
#pragma unroll
            for (int nt2 = 0; nt2 < 8; nt2++) {
                float* cc = c + (mt * 8 + nt2) * 4;
                int col = nt2 * 8 + (lane & 3) * 2;        // 0..63
#pragma unroll
                for (int h = 0; h < 2; h++) {
                    int rl = FRAG_ROW(mrow, mt, lane, h);
                    int b = rowBase + rl;
#pragma unroll
                    for (int q = 0; q < 2; q++) {
                        int ii = col + q;
                        float m = cc[h * 2 + q] + b2[ii];
                        float s = Ss[rl][ii];
                        float st = m + s * eps[b * STO + ii];
                        size_t base = (size_t)b * COUT + obase;
                        out_t[base + ii]           = m;
                        out_t[base + 2 * STO + ii] = st;
                        if (z) stoc_out[b * STO + ii] = st;
                    }
                }
            }
    }
}

// ---------------------------------------------------------------------------
extern "C" void kernel_launch(void* const* d_in, const int* in_sizes, int n_in,
                              void* d_out, int out_size)
{
    const float* actions    = (const float*)d_in[0];
    const float* nonterm    = (const float*)d_in[1];
    const float* emb        = (const float*)d_in[2];
    const float* init_deter = (const float*)d_in[3];
    const float* init_stoc  = (const float*)d_in[4];
    const float* noise_p    = (const float*)d_in[5];
    const float* noise_q    = (const float*)d_in[6];
    const float* Wi   = (const float*)d_in[7];
    const float* bi   = (const float*)d_in[8];
    const float* W_ih = (const float*)d_in[9];
    const float* W_hh = (const float*)d_in[10];
    const float* b_ih = (const float*)d_in[11];
    const float* b_hh = (const float*)d_in[12];
    const float* Wp1  = (const float*)d_in[13];
    const float* bp1  = (const float*)d_in[14];
    const float* Wp2  = (const float*)d_in[15];
    const float* bp2  = (const float*)d_in[16];
    const float* Wq1  = (const float*)d_in[17];
    const float* bq1  = (const float*)d_in[18];
    const float* Wq2  = (const float*)d_in[19];
    const float* bq2  = (const float*)d_in[20];
    float* out = (float*)d_out;

    __half *wi16, *wih16, *whh16, *wp116, *wq116, *wp216, *wq216;
    float  *deterBuf, *stocBuf;
    cudaGetSymbolAddress((void**)&wi16,  g_Wi16);
    cudaGetSymbolAddress((void**)&wih16, g_Wih16);
    cudaGetSymbolAddress((void**)&whh16, g_Whh16);
    cudaGetSymbolAddress((void**)&wp116, g_Wp116);
    cudaGetSymbolAddress((void**)&wq116, g_Wq116);
    cudaGetSymbolAddress((void**)&wp216, g_Wp216);
    cudaGetSymbolAddress((void**)&wq216, g_Wq216);
    cudaGetSymbolAddress((void**)&deterBuf, g_deter);
    cudaGetSymbolAddress((void**)&stocBuf,  g_stoc);

    auto prep = [&](const float* src, __half* dst, int N, int srcK, int dstK, int srcN, int trans) {
        int total = N * dstK;
        k_prep<<<(total + 255) / 256, 256>>>(src, dst, total, srcK, dstK, srcN, trans);
    };
    prep(Wi,   wi16,  512,  70,   128,  512, 1);
    prep(W_ih, wih16, 1536, 512,  512,  0,   0);
    prep(W_hh, whh16, 1536, 512,  512,  0,   0);
    prep(Wp1,  wp116, 512,  512,  512,  512, 1);
    prep(Wq1,  wq116, 512,  1536, 1536, 512, 1);
    prep(Wp2,  wp216, 128,  512,  512,  128, 1);
    prep(Wq2,  wq216, 128,  512,  512,  128, 1);

    for (int t = 0; t < TT; t++) {
        const float* stoc_in  = t ? stocBuf  + ((t + 1) & 1) * BBATCH * STO : init_stoc;
        const float* deter_in = t ? deterBuf + ((t + 1) & 1) * BBATCH * DET : init_deter;
        float* deter_out = deterBuf + (t & 1) * BBATCH * DET;
        float* stoc_out  = stocBuf  + (t & 1) * BBATCH * STO;
        const float* nt_t  = nonterm + (size_t)t * BBATCH;
        const float* act_t = actions + (size_t)t * BBATCH * ACTD;
        const float* emb_t = emb     + (size_t)t * BBATCH * EMBD;
        float* out_t = out + (size_t)t * BBATCH * COUT;

        kg_x   <<<dim3(8, 8),     256>>>(stoc_in, act_t, nt_t, bi);
        kg_gru <<<dim3(24, 8, 2), 256>>>(deter_in, nt_t);
        ke_gru <<<2048,           256>>>(deter_in, nt_t, b_ih, b_hh, deter_out, out_t);
        kg_mid <<<dim3(8, 8, 2),  256>>>(emb_t, bp1, bq1);
        kg_head<<<dim3(1, 8, 2),  256>>>(bp2, bq2,
                                         noise_p + (size_t)t * BBATCH * STO,
                                         noise_q + (size_t)t * BBATCH * STO,
                                         out_t, stoc_out);
    }
}

// round 7
// speedup vs baseline: 6.0305x; 1.1679x over previous
#include <cuda_runtime.h>
#include <cuda_fp16.h>
#include <math.h>
#include <stdint.h>

#define TT     64
#define BBATCH 1024
#define DET    512
#define STO    64
#define EMBD   1024
#define ACTD   6
#define MLPD   512
#define COUT   896

// ---------------- persistent scratch ----------------------------------------
__device__ __align__(16) __half g_Wi16 [512 * 128];
__device__ __align__(16) __half g_Wg16 [2 * 1536 * 512];   // gate-interleaved W_ih|W_hh
__device__ __align__(16) __half g_Wp116[512 * 512];
__device__ __align__(16) __half g_Wq116[512 * 1536];
__device__ __align__(16) __half g_Wp216[128 * 512];
__device__ __align__(16) __half g_Wq216[128 * 512];
__device__ __align__(16) __half g_x16  [BBATCH * 512];
__device__ __align__(16) __half g_det16[BBATCH * 512];
__device__ __align__(16) __half g_p116 [BBATCH * 512];
__device__ __align__(16) __half g_q116 [BBATCH * 512];
__device__ __align__(16) float  g_deter[2 * BBATCH * 512];
__device__ __align__(16) float  g_stoc [2 * BBATCH * 64];

// ---------------- math ------------------------------------------------------
__device__ __forceinline__ float eluf(float x)  { return x > 0.f ? x : expm1f(x); }
__device__ __forceinline__ float sigm(float x)  { return 1.f / (1.f + expf(-x)); }
__device__ __forceinline__ float softp(float x) { return x > 0.f ? x + log1pf(expf(-x)) : log1pf(expf(x)); }

// ---------------- MMA primitives --------------------------------------------
__device__ __forceinline__ void ldm_x4(uint32_t* r, const void* p) {
    uint32_t a;
    asm("{ .reg .u64 t; cvta.to.shared.u64 t, %1; cvt.u32.u64 %0, t; }" : "=r"(a) : "l"(p));
    asm volatile("ldmatrix.sync.aligned.m8n8.x4.shared.b16 {%0,%1,%2,%3}, [%4];"
                 : "=r"(r[0]), "=r"(r[1]), "=r"(r[2]), "=r"(r[3]) : "r"(a));
}
__device__ __forceinline__ void ldm_x2(uint32_t* r, const void* p) {
    uint32_t a;
    asm("{ .reg .u64 t; cvta.to.shared.u64 t, %1; cvt.u32.u64 %0, t; }" : "=r"(a) : "l"(p));
    asm volatile("ldmatrix.sync.aligned.m8n8.x2.shared.b16 {%0,%1}, [%2];"
                 : "=r"(r[0]), "=r"(r[1]) : "r"(a));
}
__device__ __forceinline__ void mma16816(float* c, const uint32_t* a, const uint32_t* b) {
    asm volatile(
        "mma.sync.aligned.m16n8k16.row.col.f32.f16.f16.f32 "
        "{%0,%1,%2,%3}, {%4,%5,%6,%7}, {%8,%9}, {%0,%1,%2,%3};"
        : "+f"(c[0]), "+f"(c[1]), "+f"(c[2]), "+f"(c[3])
        : "r"(a[0]), "r"(a[1]), "r"(a[2]), "r"(a[3]), "r"(b[0]), "r"(b[1]));
}

// ---------------- A-tile sources --------------------------------------------
#define SRC_F16    0
#define SRC_DETER  1
#define SRC_INPUT  2
#define SRC_CONCAT 3

template<int ASRC, int BW>
__device__ __forceinline__ void fetch_tiles64(
    int k0, int rowBase, int colBase,
    const __half* Af16, int lda,
    const float* Aa, const float* Ab, const float* nt,
    const __half* Bw, int ldb,
    uint32_t* aA, uint32_t* aB)
{
    const int tid = threadIdx.x;
#pragma unroll
    for (int i = 0; i < 8; i++) {
        int w = tid + i * 256;
        int row = w >> 5, kp = w & 31;
        int b = rowBase + row;
        int k = k0 + kp * 2;
        __half2 v;
        if (ASRC == SRC_F16) {
            v = *(const __half2*)(Af16 + (size_t)b * lda + k);
        } else if (ASRC == SRC_DETER) {
            float2 f = *(const float2*)(Aa + (size_t)b * DET + k);
            float s = nt[b];
            v = __floats2half2_rn(f.x * s, f.y * s);
        } else if (ASRC == SRC_CONCAT) {
            if (k < DET) {
                v = *(const __half2*)(Af16 + (size_t)b * DET + k);
            } else {
                float2 f = *(const float2*)(Aa + (size_t)b * EMBD + (k - DET));
                v = __floats2half2_rn(f.x, f.y);
            }
        } else { // SRC_INPUT
            float s = nt[b];
            float lo = (k < STO) ? Aa[b * STO + k] * s
                     : ((k < STO + ACTD) ? Ab[b * ACTD + (k - STO)] : 0.f);
            int k1 = k + 1;
            float hi = (k1 < STO) ? Aa[b * STO + k1] * s
                     : ((k1 < STO + ACTD) ? Ab[b * ACTD + (k1 - STO)] : 0.f);
            v = __floats2half2_rn(lo, hi);
        }
        aA[i] = *(uint32_t*)&v;
    }
#pragma unroll
    for (int i = 0; i < BW; i++) {
        int w = tid + i * 256;
        int row = w >> 5, kp = w & 31;
        __half2 v = *(const __half2*)(Bw + (size_t)(colBase + row) * ldb + k0 + kp * 2);
        aB[i] = *(uint32_t*)&v;
    }
}

// ---- C[64 x NCOLS] = A[64xK] * B[NCOLS x K]^T; 8 warps: wm=w&3 (16 rows),
// ---- wn=w>>2 (NCOLS/2 cols). cacc[NT*4], NT = NCOLS/16.
template<int NCOLS, int ASRC>
__device__ __forceinline__ void gemm_core64(
    int kchunks,
    const __half* Af16, int lda,
    const float* Aa, const float* Ab, const float* nt,
    const __half* Bw, int ldb,
    int rowBase, int colBase,
    __half (*sA)[72], __half (*sB)[72],
    float* cacc)
{
    constexpr int BW = NCOLS / 8;
    constexpr int NT = NCOLS / 16;
    const int tid = threadIdx.x, lane = tid & 31, w = tid >> 5;
    const int mrow = (w & 3) * 16;
    const int ncol = (w >> 2) * (NCOLS / 2);

#pragma unroll
    for (int i = 0; i < NT * 4; i++) cacc[i] = 0.f;

    uint32_t aA[8], aB[BW];
    fetch_tiles64<ASRC, BW>(0, rowBase, colBase, Af16, lda, Aa, Ab, nt, Bw, ldb, aA, aB);

    for (int c = 0; c < kchunks; c++) {
#pragma unroll
        for (int i = 0; i < 8; i++) {
            int ww = tid + i * 256;
            *(uint32_t*)&sA[ww >> 5][(ww & 31) * 2] = aA[i];
        }
#pragma unroll
        for (int i = 0; i < BW; i++) {
            int ww = tid + i * 256;
            *(uint32_t*)&sB[ww >> 5][(ww & 31) * 2] = aB[i];
        }
        __syncthreads();
#pragma unroll
        for (int kk = 0; kk < 4; kk++) {
            int kb = kk * 16;
            uint32_t afr[4];
            ldm_x4(afr, &sA[mrow + (lane & 15)][kb + ((lane >> 4) << 3)]);
            uint32_t bfr[NT][2];
#pragma unroll
            for (int nt2 = 0; nt2 < NT; nt2++)
                ldm_x2(bfr[nt2], &sB[ncol + nt2 * 8 + (lane & 7)][kb + (((lane >> 3) & 1) << 3)]);
#pragma unroll
            for (int nt2 = 0; nt2 < NT; nt2++)
                mma16816(cacc + nt2 * 4, afr, bfr[nt2]);
        }
        if (c + 1 < kchunks)
            fetch_tiles64<ASRC, BW>((c + 1) * 64, rowBase, colBase,
                                    Af16, lda, Aa, Ab, nt, Bw, ldb, aA, aB);
        __syncthreads();
    }
}

#define FROW(wm16, lane, h) ((wm16) + ((lane) >> 2) + ((h) ? 8 : 0))
#define FCOL(nc, nt2, lane) ((nc) + (nt2) * 8 + ((lane) & 3) * 2)

// ---------------- prep kernels ----------------------------------------------
__global__ __launch_bounds__(256) void k_prep(
    const float* __restrict__ src, __half* __restrict__ dst,
    int total, int srcK, int dstK, int srcN, int trans)
{
    for (int idx = blockIdx.x * 256 + threadIdx.x; idx < total; idx += gridDim.x * 256) {
        int n = idx / dstK, k = idx % dstK;
        float v = 0.f;
        if (k < srcK)
            v = trans ? src[(size_t)k * srcN + n] : src[(size_t)n * srcK + k];
        dst[idx] = __float2half(v);
    }
}

// gate-interleave: dst row rr = jb*192 + gate*64 + jj  <-  src row gate*512 + jb*64 + jj
__global__ __launch_bounds__(256) void k_prep_gru(
    const float* __restrict__ Wih, const float* __restrict__ Whh,
    __half* __restrict__ dst)
{
    int total = 1536 * 512;
    for (int idx = blockIdx.x * 256 + threadIdx.x; idx < total; idx += gridDim.x * 256) {
        int rr = idx / 512, k = idx % 512;
        int jb = rr / 192, rem = rr % 192;
        int gate = rem >> 6, jj = rem & 63;
        int srow = gate * 512 + jb * 64 + jj;
        dst[idx]               = __float2half(Wih[(size_t)srow * 512 + k]);
        dst[total + idx]       = __float2half(Whh[(size_t)srow * 512 + k]);
    }
}

// ---------------- step kernels ----------------------------------------------

// G1: x16 = fp16(ELU(cat(stoc*nt, act) @ Wi + bi))   grid(8,16), NCOLS=64
__global__ __launch_bounds__(256) void kg_x(
    const float* __restrict__ stoc_in, const float* __restrict__ act_t,
    const float* __restrict__ nt, const float* __restrict__ bi)
{
    __shared__ __align__(16) __half sA[64][72];
    __shared__ __align__(16) __half sB[64][72];
    int rowBase = blockIdx.y * 64, colBase = blockIdx.x * 64;
    float c[16];
    gemm_core64<64, SRC_INPUT>(2, nullptr, 0, stoc_in, act_t, nt,
                               g_Wi16, 128, rowBase, colBase, sA, sB, c);
    int lane = threadIdx.x & 31, w = threadIdx.x >> 5;
    int wm16 = (w & 3) * 16, nc = (w >> 2) * 32;
#pragma unroll
    for (int nt2 = 0; nt2 < 4; nt2++) {
        int col = colBase + FCOL(nc, nt2, lane);
#pragma unroll
        for (int h = 0; h < 2; h++) {
            int b = rowBase + FROW(wm16, lane, h);
            float v0 = eluf(c[nt2 * 4 + h * 2]     + bi[col]);
            float v1 = eluf(c[nt2 * 4 + h * 2 + 1] + bi[col + 1]);
            *(__half2*)(g_x16 + (size_t)b * 512 + col) = __floats2half2_rn(v0, v1);
        }
    }
}

// G2: fused GRU: gi = x@W_ih^T, gh = h@W_hh^T, gates, deter_new.  grid(8,16)
// CTA: 64 rows x 192 cols (= 3 gates x 64 j). K chunks of 32.
__global__ __launch_bounds__(256) void kg_gruf(
    const float* __restrict__ deter_in, const float* __restrict__ nt,
    const float* __restrict__ b_ih, const float* __restrict__ b_hh,
    float* __restrict__ deter_out, float* __restrict__ out_t)
{
    __shared__ __align__(16) unsigned char raw[40960];
    __half (*sAx)[40]  = (__half(*)[40])(raw);
    __half (*sAh)[40]  = (__half(*)[40])(raw + 5120);
    __half (*sBi)[40]  = (__half(*)[40])(raw + 10240);
    __half (*sBh)[40]  = (__half(*)[40])(raw + 10240 + 15360);

    const int tid = threadIdx.x, lane = tid & 31, w = tid >> 5;
    const int wm16 = (w & 3) * 16, wn = w >> 2;           // wn in {0,1}: 96 cols
    const int rowBase = blockIdx.y * 64;
    const int cb192 = blockIdx.x * 192;                   // B-row base
    const int jb64  = blockIdx.x * 64;                    // j base

    float cgi[48], cgh[48];
#pragma unroll
    for (int i = 0; i < 48; i++) { cgi[i] = 0.f; cgh[i] = 0.f; }

    const __half* Bih = g_Wg16;
    const __half* Bhh = g_Wg16 + 1536 * 512;

    for (int c = 0; c < 16; c++) {
        int k0 = c * 32;
#pragma unroll
        for (int i = 0; i < 4; i++) {
            int ww = tid + i * 256;
            int row = ww >> 4, kp = ww & 15;
            int b = rowBase + row, k = k0 + kp * 2;
            *(uint32_t*)&sAx[row][kp * 2] =
                *(const uint32_t*)(g_x16 + (size_t)b * 512 + k);
            float2 f = *(const float2*)(deter_in + (size_t)b * DET + k);
            float s = nt[b];
            __half2 v = __floats2half2_rn(f.x * s, f.y * s);
            *(uint32_t*)&sAh[row][kp * 2] = *(uint32_t*)&v;
        }
#pragma unroll
        for (int i = 0; i < 12; i++) {
            int ww = tid + i * 256;
            int row = ww >> 4, kp = ww & 15;
            int k = k0 + kp * 2;
            *(uint32_t*)&sBi[row][kp * 2] =
                *(const uint32_t*)(Bih + (size_t)(cb192 + row) * 512 + k);
            *(uint32_t*)&sBh[row][kp * 2] =
                *(const uint32_t*)(Bhh + (size_t)(cb192 + row) * 512 + k);
        }
        __syncthreads();
#pragma unroll
        for (int kk = 0; kk < 2; kk++) {
            int kb = kk * 16;
            uint32_t afx[4], afh[4];
            ldm_x4(afx, &sAx[wm16 + (lane & 15)][kb + ((lane >> 4) << 3)]);
            ldm_x4(afh, &sAh[wm16 + (lane & 15)][kb + ((lane >> 4) << 3)]);
#pragma unroll
            for (int nt2 = 0; nt2 < 12; nt2++) {
                uint32_t bf[2];
                ldm_x2(bf, &sBi[wn * 96 + nt2 * 8 + (lane & 7)][kb + (((lane >> 3) & 1) << 3)]);
                mma16816(cgi + nt2 * 4, afx, bf);
                ldm_x2(bf, &sBh[wn * 96 + nt2 * 8 + (lane & 7)][kb + (((lane >> 3) & 1) << 3)]);
                mma16816(cgh + nt2 * 4, afh, bf);
            }
        }
        __syncthreads();
    }

    // ---- gate epilogue: exchange r,z via smem (overlay on tile smem) ----
    float (*rS)[65] = (float(*)[65])(raw);
    float (*zS)[65] = (float(*)[65])(raw + 64 * 65 * 4);

#pragma unroll
    for (int nt2 = 0; nt2 < 12; nt2++) {
#pragma unroll
        for (int h = 0; h < 2; h++) {
            int row = FROW(wm16, lane, h);
#pragma unroll
            for (int q = 0; q < 2; q++) {
                int col = wn * 96 + nt2 * 8 + (lane & 3) * 2 + q;
                int gate = col >> 6, jj = col & 63;
                int j = jb64 + jj;
                float gi = cgi[nt2 * 4 + h * 2 + q];
                float gh = cgh[nt2 * 4 + h * 2 + q];
                if (gate == 0)
                    rS[row][jj] = sigm(gi + gh + b_ih[j] + b_hh[j]);
                else if (gate == 1)
                    zS[row][jj] = sigm(gi + gh + b_ih[512 + j] + b_hh[512 + j]);
            }
        }
    }
    __syncthreads();
#pragma unroll
    for (int nt2 = 0; nt2 < 12; nt2++) {
#pragma unroll
        for (int h = 0; h < 2; h++) {
            int row = FROW(wm16, lane, h);
            int b = rowBase + row;
#pragma unroll
            for (int q = 0; q < 2; q++) {
                int col = wn * 96 + nt2 * 8 + (lane & 3) * 2 + q;
                int gate = col >> 6, jj = col & 63;
                if (gate == 2) {
                    int j = jb64 + jj;
                    float inn = cgi[nt2 * 4 + h * 2 + q] + b_ih[1024 + j];
                    float hn  = cgh[nt2 * 4 + h * 2 + q] + b_hh[1024 + j];
                    float r = rS[row][jj];
                    float z = zS[row][jj];
                    float n = tanhf(inn + r * hn);
                    float hv = deter_in[(size_t)b * DET + j] * nt[b];
                    float dn = (1.f - z) * n + z * hv;
                    deter_out[(size_t)b * DET + j] = dn;
                    g_det16[(size_t)b * 512 + j] = __float2half(dn);
                    out_t[(size_t)b * COUT + j] = dn;
                }
            }
        }
    }
}

// G3: p1 (z=0, K=512) / q1 (z=1, K=1536)   grid(8,16,2)
__global__ __launch_bounds__(256) void kg_mid(
    const float* __restrict__ emb_t,
    const float* __restrict__ bp1, const float* __restrict__ bq1)
{
    __shared__ __align__(16) __half sA[64][72];
    __shared__ __align__(16) __half sB[64][72];
    int z = blockIdx.z;
    int rowBase = blockIdx.y * 64, colBase = blockIdx.x * 64;
    float c[16];
    if (z)
        gemm_core64<64, SRC_CONCAT>(24, g_det16, 512, emb_t, nullptr, nullptr,
                                    g_Wq116, 1536, rowBase, colBase, sA, sB, c);
    else
        gemm_core64<64, SRC_F16>(8, g_det16, 512, nullptr, nullptr, nullptr,
                                 g_Wp116, 512, rowBase, colBase, sA, sB, c);
    const float* bia = z ? bq1 : bp1;
    __half* outp = z ? g_q116 : g_p116;
    int lane = threadIdx.x & 31, w = threadIdx.x >> 5;
    int wm16 = (w & 3) * 16, nc = (w >> 2) * 32;
#pragma unroll
    for (int nt2 = 0; nt2 < 4; nt2++) {
        int col = colBase + FCOL(nc, nt2, lane);
#pragma unroll
        for (int h = 0; h < 2; h++) {
            int b = rowBase + FROW(wm16, lane, h);
            float v0 = eluf(c[nt2 * 4 + h * 2]     + bia[col]);
            float v1 = eluf(c[nt2 * 4 + h * 2 + 1] + bia[col + 1]);
            *(__half2*)(outp + (size_t)b * 512 + col) = __floats2half2_rn(v0, v1);
        }
    }
}

// G4: heads.  z=0 prior, z=1 posterior.  grid(1,16,2), NCOLS=128.
__global__ __launch_bounds__(256) void kg_head(
    const float* __restrict__ bp2, const float* __restrict__ bq2,
    const float* __restrict__ eps_p, const float* __restrict__ eps_q,
    float* __restrict__ out_t, float* __restrict__ stoc_out)
{
    __shared__ __align__(16) unsigned char raw[64 * 72 * 2 + 128 * 72 * 2];
    __half (*sA)[72] = (__half(*)[72])(raw);
    __half (*sB)[72] = (__half(*)[72])(raw + 64 * 72 * 2);
    int z = blockIdx.z;
    int rowBase = blockIdx.y * 64;
    float c[32];
    if (z)
        gemm_core64<128, SRC_F16>(8, g_q116, 512, nullptr, nullptr, nullptr,
                                  g_Wq216, 512, rowBase, 0, sA, sB, c);
    else
        gemm_core64<128, SRC_F16>(8, g_p116, 512, nullptr, nullptr, nullptr,
                                  g_Wp216, 512, rowBase, 0, sA, sB, c);
    const float* b2  = z ? bq2 : bp2;
    const float* eps = z ? eps_q : eps_p;
    const int obase  = z ? (DET + 3 * STO) : DET;
    int lane = threadIdx.x & 31, w = threadIdx.x >> 5;
    int wm16 = (w & 3) * 16, wn = w >> 2;

    float (*Ss)[65] = (float(*)[65])(raw);
    __syncthreads();

    if (wn == 1) { // std cols 64..127
#pragma unroll
        for (int nt2 = 0; nt2 < 8; nt2++) {
#pragma unroll
            for (int h = 0; h < 2; h++) {
                int row = FROW(wm16, lane, h);
                int b = rowBase + row;
#pragma unroll
                for (int q = 0; q < 2; q++) {
                    int col = 64 + nt2 * 8 + (lane & 3) * 2 + q;
                    int ii = col - 64;
                    float s = softp(c[nt2 * 4 + h * 2 + q] + b2[col]) + 0.1f;
                    Ss[row][ii] = s;
                    out_t[(size_t)b * COUT + obase + STO + ii] = s;
                }
            }
        }
    }
    __syncthreads();
    if (wn == 0) { // mean cols 0..63
#pragma unroll
        for (int nt2 = 0; nt2 < 8; nt2++) {
#pragma unroll
            for (int h = 0; h < 2; h++) {
                int row = FROW(wm16, lane, h);
                int b = rowBase + row;
#pragma unroll
                for (int q = 0; q < 2; q++) {
                    int ii = nt2 * 8 + (lane & 3) * 2 + q;
                    float m = c[nt2 * 4 + h * 2 + q] + b2[ii];
                    float s = Ss[row][ii];
                    float st = m + s * eps[b * STO + ii];
                    size_t base = (size_t)b * COUT + obase;
                    out_t[base + ii]           = m;
                    out_t[base + 2 * STO + ii] = st;
                    if (z) stoc_out[b * STO + ii] = st;
                }
            }
        }
    }
}

// ---------------------------------------------------------------------------
extern "C" void kernel_launch(void* const* d_in, const int* in_sizes, int n_in,
                              void* d_out, int out_size)
{
    const float* actions    = (const float*)d_in[0];
    const float* nonterm    = (const float*)d_in[1];
    const float* emb        = (const float*)d_in[2];
    const float* init_deter = (const float*)d_in[3];
    const float* init_stoc  = (const float*)d_in[4];
    const float* noise_p    = (const float*)d_in[5];
    const float* noise_q    = (const float*)d_in[6];
    const float* Wi   = (const float*)d_in[7];
    const float* bi   = (const float*)d_in[8];
    const float* W_ih = (const float*)d_in[9];
    const float* W_hh = (const float*)d_in[10];
    const float* b_ih = (const float*)d_in[11];
    const float* b_hh = (const float*)d_in[12];
    const float* Wp1  = (const float*)d_in[13];
    const float* bp1  = (const float*)d_in[14];
    const float* Wp2  = (const float*)d_in[15];
    const float* bp2  = (const float*)d_in[16];
    const float* Wq1  = (const float*)d_in[17];
    const float* bq1  = (const float*)d_in[18];
    const float* Wq2  = (const float*)d_in[19];
    const float* bq2  = (const float*)d_in[20];
    float* out = (float*)d_out;

    __half *wi16, *wg16, *wp116, *wq116, *wp216, *wq216;
    float  *deterBuf, *stocBuf;
    cudaGetSymbolAddress((void**)&wi16,  g_Wi16);
    cudaGetSymbolAddress((void**)&wg16,  g_Wg16);
    cudaGetSymbolAddress((void**)&wp116, g_Wp116);
    cudaGetSymbolAddress((void**)&wq116, g_Wq116);
    cudaGetSymbolAddress((void**)&wp216, g_Wp216);
    cudaGetSymbolAddress((void**)&wq216, g_Wq216);
    cudaGetSymbolAddress((void**)&deterBuf, g_deter);
    cudaGetSymbolAddress((void**)&stocBuf,  g_stoc);

    auto prep = [&](const float* src, __half* dst, int N, int srcK, int dstK, int srcN, int trans) {
        int total = N * dstK;
        k_prep<<<(total + 255) / 256, 256>>>(src, dst, total, srcK, dstK, srcN, trans);
    };
    prep(Wi,  wi16,  512, 70,   128,  512, 1);
    prep(Wp1, wp116, 512, 512,  512,  512, 1);
    prep(Wq1, wq116, 512, 1536, 1536, 512, 1);
    prep(Wp2, wp216, 128, 512,  512,  128, 1);
    prep(Wq2, wq216, 128, 512,  512,  128, 1);
    k_prep_gru<<<1024, 256>>>(W_ih, W_hh, wg16);

    for (int t = 0; t < TT; t++) {
        const float* stoc_in  = t ? stocBuf  + ((t + 1) & 1) * BBATCH * STO : init_stoc;
        const float* deter_in = t ? deterBuf + ((t + 1) & 1) * BBATCH * DET : init_deter;
        float* deter_out = deterBuf + (t & 1) * BBATCH * DET;
        float* stoc_out  = stocBuf  + (t & 1) * BBATCH * STO;
        const float* nt_t  = nonterm + (size_t)t * BBATCH;
        const float* act_t = actions + (size_t)t * BBATCH * ACTD;
        const float* emb_t = emb     + (size_t)t * BBATCH * EMBD;
        float* out_t = out + (size_t)t * BBATCH * COUT;

        kg_x   <<<dim3(8, 16),    256>>>(stoc_in, act_t, nt_t, bi);
        kg_gruf<<<dim3(8, 16),    256>>>(deter_in, nt_t, b_ih, b_hh, deter_out, out_t);
        kg_mid <<<dim3(8, 16, 2), 256>>>(emb_t, bp1, bq1);
        kg_head<<<dim3(1, 16, 2), 256>>>(bp2, bq2,
                                         noise_p + (size_t)t * BBATCH * STO,
                                         noise_q + (size_t)t * BBATCH * STO,
                                         out_t, stoc_out);
    }
}